// round 10
// baseline (speedup 1.0000x reference)
#include <cuda_runtime.h>
#include <cuda_fp16.h>
#include <stdint.h>

// Problem constants
#define IC    384
#define OCC   384
#define NB    32
#define IH    64
#define IW    64
#define OH    32
#define OW    32
#define KTOT  (IC * 9)          // 3456
#define NWEI  (OCC * KTOT)      // 1327104
#define NTOT  (NB * OH * OW)    // 32768

// GEMM tiling: CTA = 128(M) x 128(N) x 32(K), 8 warps of 64x32, occupancy 2
#define BM    128
#define BN    128
#define BK    32
#define NKB   (KTOT / BK)       // 108
#define NTILE ((NTOT / BN) * 3) // 768 logical tiles
#define GRID  296               // persistent: 2 CTAs x 148 SMs
#define S     5                 // cp.async pipeline stages
#define ASTR  40                // halves per A smem row (80B, 16B-aligned, LDSM CF)
#define BSTR  136               // halves per B smem row (272B = 17 odd units, LDSM CF)
#define ABYTES (BM * ASTR * 2)  // 10240
#define BBYTES (BK * BSTR * 2)  // 8704
#define STAGE  (ABYTES + BBYTES)          // 18944
#define SMEM_TOTAL (S * STAGE)            // 94720 (x2 CTAs = 189KB/SM)

#define KWSZ ((size_t)NB * IC * 66 * 32)  // halves per kw plane
#define PREP_BLOCKS 49920                 // NB*IC*65*16/256
#define QUANT_BLOCKS 5184                 // ceil(NWEI/256)

// Scratch (device globals: allocation-free contract)
__device__ float  g_alpha;
__device__ float  g_part[256];
__device__ __half g_wq[(size_t)NKB * OCC * BK];  // [kb32][oc][32] ternary fp16
__device__ __half g_xq[3 * KWSZ];                // [kw][b][ic][row 0..65][ox 0..31]

// ---------------------------------------------------------------------------
// Stage 1: deterministic |w| reduction -> alpha
// ---------------------------------------------------------------------------
__global__ void abssum_part(const float* __restrict__ w) {
    __shared__ float sm[256];
    const int tid = threadIdx.x;
    float s = 0.f;
    for (int i = blockIdx.x * 256 + tid; i < NWEI; i += 256 * 256)
        s += fabsf(w[i]);
    sm[tid] = s;
    __syncthreads();
    #pragma unroll
    for (int o = 128; o > 0; o >>= 1) {
        if (tid < o) sm[tid] += sm[tid + o];
        __syncthreads();
    }
    if (tid == 0) g_part[blockIdx.x] = sm[0];
}

__global__ void abssum_fin() {
    __shared__ float sm[256];
    const int tid = threadIdx.x;
    sm[tid] = g_part[tid];
    __syncthreads();
    #pragma unroll
    for (int o = 128; o > 0; o >>= 1) {
        if (tid < o) sm[tid] += sm[tid + o];
        __syncthreads();
    }
    if (tid == 0) g_alpha = sm[0] / (float)NWEI;
}

// ---------------------------------------------------------------------------
// Stage 2 (merged): ternary quantize + x fp16 prep, one launch.
// ---------------------------------------------------------------------------
__global__ void prep_and_quant(const float* __restrict__ x,
                               const float* __restrict__ w) {
    const int tid = threadIdx.x;
    if (blockIdx.x < PREP_BLOCKS) {
        const int idx = blockIdx.x * 256 + tid;
        const int t = idx & 15;             // ox pair (2t, 2t+1)
        const int r = idx >> 4;             // row id over NB*IC*65
        const int iy = r % 65 - 1;          // -1..63
        const int bc = r / 65;              // b*IC + ic
        const size_t orow = ((size_t)bc * 66 + (iy + 1)) * 32 + 2 * t;

        __half2 h0, h1, h2;
        if (iy < 0) {
            h0 = h1 = h2 = __floats2half2_rn(0.f, 0.f);
        } else {
            const float* xr = x + ((size_t)bc * IH + iy) * IW;
            const float4 v = *reinterpret_cast<const float4*>(xr + 4 * t);
            const float prev = (t > 0) ? xr[4 * t - 1] : 0.f;
            h0 = __floats2half2_rn(prev, v.y);   // kw=0: ix = 2ox-1
            h1 = __floats2half2_rn(v.x,  v.z);   // kw=1: ix = 2ox
            h2 = __floats2half2_rn(v.y,  v.w);   // kw=2: ix = 2ox+1
        }
        *reinterpret_cast<__half2*>(g_xq + 0 * KWSZ + orow) = h0;
        *reinterpret_cast<__half2*>(g_xq + 1 * KWSZ + orow) = h1;
        *reinterpret_cast<__half2*>(g_xq + 2 * KWSZ + orow) = h2;
    } else {
        const int j = (blockIdx.x - PREP_BLOCKS) * 256 + tid;
        if (j >= NWEI) return;
        const float thr = 0.001f * g_alpha;
        const int oc  = j / KTOT;
        const int r   = j - oc * KTOT;
        const int tap = r / IC;
        const int ic  = r - tap * IC;
        const float wv = w[oc * KTOT + ic * 9 + tap];     // OIHW linear
        const float q = (wv > thr) ? 1.f : ((wv < -thr) ? -1.f : 0.f);
        const int kb = tap * 12 + (ic >> 5);
        g_wq[((size_t)kb * OCC + oc) * BK + (ic & 31)] = __float2half_rn(q);
    }
}

// ---------------------------------------------------------------------------
// Stage 3: persistent implicit-GEMM conv; fragments software-pipelined in
// registers so every warp's LDSM issues under its own HMMA stream.
// ---------------------------------------------------------------------------
__device__ __forceinline__ void cp16(uint32_t dst, const void* src) {
    asm volatile("cp.async.cg.shared.global [%0], [%1], 16;\n"
                 :: "r"(dst), "l"(src) : "memory");
}
__device__ __forceinline__ void ldsmA(uint32_t* f, uint32_t addr) {
    asm volatile("ldmatrix.sync.aligned.m8n8.x4.shared.b16 {%0,%1,%2,%3}, [%4];\n"
                 : "=r"(f[0]), "=r"(f[1]), "=r"(f[2]), "=r"(f[3]) : "r"(addr));
}
__device__ __forceinline__ void ldsmBT(uint32_t* f, uint32_t addr) {
    asm volatile("ldmatrix.sync.aligned.m8n8.x4.trans.shared.b16 {%0,%1,%2,%3}, [%4];\n"
                 : "=r"(f[0]), "=r"(f[1]), "=r"(f[2]), "=r"(f[3]) : "r"(addr));
}

__global__ __launch_bounds__(256, 2)
void conv_mma7(const float* __restrict__ bias, float* __restrict__ out)
{
    extern __shared__ char smem_raw[];
    const uint32_t sbase = (uint32_t)__cvta_generic_to_shared(smem_raw);

    const int tid  = threadIdx.x;
    const int lane = tid & 31;
    const int wid  = tid >> 5;
    const int wm   = wid >> 2;          // 0..1
    const int wn   = wid & 3;           // 0..3

    // cp.async per-thread invariants
    const int am0 = tid >> 2, ac = tid & 3;
    const uint32_t adst0 = sbase + (uint32_t)(am0 * ASTR + ac * 8) * 2;
    const int kB0 = tid >> 4, nc = tid & 15;
    const uint32_t bdst0 = sbase + (uint32_t)ABYTES + (uint32_t)(kB0 * BSTR + nc * 8) * 2;

    // ldmatrix per-lane byte offsets (A: +ms*16 rows, +step*16 cols handled per call)
    const int arow  = wm * 64 + ((lane >> 3) & 1) * 8 + (lane & 7);
    const int acol  = (lane >> 4) * 8;
    const int brow  = ((lane >> 3) & 1) * 8 + (lane & 7);
    const int bcolh = wn * 32 + (lane >> 4) * 8;
    const uint32_t laneA = (uint32_t)(arow * ASTR + acol) * 2;
    const uint32_t laneB = (uint32_t)(brow * BSTR + bcolh) * 2;

    const int g  = lane >> 2;
    const int tq = lane & 3;
    const float alpha = g_alpha;

    // fragment ring buffers
    uint32_t afr[2][2][4];   // [buf][ms-within-half][4]
    uint32_t bfr[2][2][4];   // [buf][nb][4]
    float acc[4][4][4];

    #pragma unroll 1
    for (int tile = blockIdx.x; tile < NTILE; tile += GRID) {
        const int m_tile = tile % 3;        // consecutive tiles share B slab in L2
        const int n_tile = tile / 3;
        const int oc0  = m_tile * BM;
        const int n0   = n_tile * BN;
        const int bimg = n0 >> 10;
        const int pos0 = n0 & 1023;
        const int oy0  = pos0 >> 5;

        const size_t aoff0 = (size_t)(oc0 + am0) * BK + ac * 8;
        const int    oyc   = oy0 + (nc >> 2);
        const size_t boff0 = ((size_t)(bimg * IC + kB0) * 66 + 2 * oyc) * 32 + (nc & 3) * 8;

        #pragma unroll
        for (int i = 0; i < 4; i++)
            #pragma unroll
            for (int j = 0; j < 4; j++)
                #pragma unroll
                for (int c = 0; c < 4; c++)
                    acc[i][j][c] = 0.f;

        auto issue = [&](int kb, int s) {
            const int tap = kb / 12;                 // 0..8
            const int icb = (kb - tap * 12) << 5;
            const int kh  = tap / 3;
            const int kw  = tap - kh * 3;
            const __half* wsrc = g_wq + (size_t)kb * (OCC * BK) + aoff0;
            const __half* xsrc = g_xq + (size_t)kw * KWSZ + boff0
                               + (size_t)icb * (66 * 32) + kh * 32;
            const uint32_t st = (uint32_t)(s * STAGE);
            cp16(adst0 + st,                     wsrc);
            cp16(adst0 + st + (64 * ASTR * 2),   wsrc + 64 * BK);
            cp16(bdst0 + st,                     xsrc);
            cp16(bdst0 + st + (16 * BSTR * 2),   xsrc + (size_t)16 * (66 * 32));
            asm volatile("cp.async.commit_group;\n" ::: "memory");
        };

        // ld A half (2 fragments, ms = 2h, 2h+1) at (stage base, step)
        auto ldAh = [&](uint32_t fr[2][4], uint32_t aB, int step, int h) {
            ldsmA(fr[0], aB + laneA + (uint32_t)(((h * 2 + 0) * 16 * ASTR) + step * 16) * 2);
            ldsmA(fr[1], aB + laneA + (uint32_t)(((h * 2 + 1) * 16 * ASTR) + step * 16) * 2);
        };
        auto ldBs = [&](uint32_t fr[2][4], uint32_t bB, int step) {
            ldsmBT(fr[0], bB + laneB + (uint32_t)(step * 16 * BSTR) * 2);
            ldsmBT(fr[1], bB + laneB + (uint32_t)(step * 16 * BSTR + 16) * 2);
        };
        // 8 HMMAs: half h of the m-tile with fragments a2 (2 frags) and b2 (full step B)
        auto hmma8 = [&](int h, uint32_t a2[2][4], uint32_t b2[2][4]) {
            #pragma unroll
            for (int m2 = 0; m2 < 2; m2++)
                #pragma unroll
                for (int ns = 0; ns < 4; ns++)
                    asm volatile(
                        "mma.sync.aligned.m16n8k16.row.col.f32.f16.f16.f32 "
                        "{%0,%1,%2,%3}, {%4,%5,%6,%7}, {%8,%9}, {%0,%1,%2,%3};\n"
                        : "+f"(acc[h * 2 + m2][ns][0]), "+f"(acc[h * 2 + m2][ns][1]),
                          "+f"(acc[h * 2 + m2][ns][2]), "+f"(acc[h * 2 + m2][ns][3])
                        : "r"(a2[m2][0]), "r"(a2[m2][1]), "r"(a2[m2][2]), "r"(a2[m2][3]),
                          "r"(b2[ns >> 1][(ns & 1) * 2]),
                          "r"(b2[ns >> 1][(ns & 1) * 2 + 1]));
        };

        // tile boundary: ring buffers from previous tile still being read
        __syncthreads();

        // prologue: fill S-1 stages, establish visibility of stages 0,1, preload
        #pragma unroll
        for (int p = 0; p < S - 1; p++) issue(p, p);
        asm volatile("cp.async.wait_group %0;\n" :: "n"(S - 3) : "memory");
        __syncthreads();
        ldAh(afr[0], sbase, 0, 0);                 // (kb0, step0, h0)
        ldBs(bfr[0], sbase + (uint32_t)ABYTES, 0); // (kb0, step0) B

        #pragma unroll 1
        for (int kb = 0; kb < NKB; kb++) {
            if (kb + (S - 1) < NKB)
                issue(kb + (S - 1), (kb + (S - 1)) % S);
            else
                asm volatile("cp.async.commit_group;\n" ::: "memory");

            const uint32_t aC = sbase + (uint32_t)((kb % S) * STAGE);
            const uint32_t bC = aC + (uint32_t)ABYTES;
            const uint32_t aN = sbase + (uint32_t)(((kb + 1) % S) * STAGE);
            const uint32_t bN = aN + (uint32_t)ABYTES;
            // (stage kb+1 data is stale-read-safe at kb==NKB-1; results unused)

            // HS0: prefetch (kb,0,h1); HMMA (kb,0,h0)
            ldAh(afr[1], aC, 0, 1);
            hmma8(0, afr[0], bfr[0]);
            // HS1: prefetch B(kb,1) + (kb,1,h0); HMMA (kb,0,h1)
            ldBs(bfr[1], bC, 1);
            ldAh(afr[0], aC, 1, 0);
            hmma8(1, afr[1], bfr[0]);
            // HS2: prefetch (kb,1,h1); HMMA (kb,1,h0)
            ldAh(afr[1], aC, 1, 1);
            hmma8(0, afr[0], bfr[1]);
            // HS3: prefetch B(kb+1,0) + (kb+1,0,h0); HMMA (kb,1,h1)
            ldBs(bfr[0], bN, 0);
            ldAh(afr[0], aN, 0, 0);
            hmma8(1, afr[1], bfr[1]);

            if (kb + 1 < NKB) {
                // stages <= kb+2 complete after this; barrier publishes them and
                // protects stage (kb+S)%S buffer before next iter's issue
                asm volatile("cp.async.wait_group %0;\n" :: "n"(S - 3) : "memory");
                __syncthreads();
            }
        }

        // epilogue: out = alpha*acc + bias (regs->gmem only; no smem hazard)
        float* ob = out + (size_t)bimg * OCC * (OH * OW);
        #pragma unroll
        for (int ms = 0; ms < 4; ms++) {
            const int oc_a = oc0 + wm * 64 + ms * 16 + g;
            const int oc_b = oc_a + 8;
            const float ba = bias[oc_a];
            const float bc = bias[oc_b];
            #pragma unroll
            for (int ns = 0; ns < 4; ns++) {
                const int pcol = pos0 + wn * 32 + ns * 8 + tq * 2;
                float2 v0, v1;
                v0.x = alpha * acc[ms][ns][0] + ba;
                v0.y = alpha * acc[ms][ns][1] + ba;
                v1.x = alpha * acc[ms][ns][2] + bc;
                v1.y = alpha * acc[ms][ns][3] + bc;
                *reinterpret_cast<float2*>(ob + (size_t)oc_a * (OH * OW) + pcol) = v0;
                *reinterpret_cast<float2*>(ob + (size_t)oc_b * (OH * OW) + pcol) = v1;
            }
        }
    }
}

// ---------------------------------------------------------------------------
extern "C" void kernel_launch(void* const* d_in, const int* in_sizes, int n_in,
                              void* d_out, int out_size)
{
    (void)in_sizes; (void)n_in; (void)out_size;
    const float* x      = (const float*)d_in[0];
    const float* weight = (const float*)d_in[1];
    const float* bias   = (const float*)d_in[2];
    float* out = (float*)d_out;

    cudaFuncSetAttribute(conv_mma7, cudaFuncAttributeMaxDynamicSharedMemorySize, SMEM_TOTAL);

    abssum_part<<<256, 256>>>(weight);                        // launch 1
    abssum_fin<<<1, 256>>>();                                 // launch 2
    prep_and_quant<<<PREP_BLOCKS + QUANT_BLOCKS, 256>>>(x, weight);  // launch 3
    conv_mma7<<<GRID, 256, SMEM_TOTAL>>>(bias, out);          // launch 4 -> ncu captures this
}